// round 7
// baseline (speedup 1.0000x reference)
#include <cuda_runtime.h>
#include <cuda_bf16.h>
#include <cstdint>

#define D  512
#define DD (D * D)

#if !defined(__CUDA_ARCH__) || defined(__CUDA_ARCH_FEAT_SM103_ALL) || defined(__CUDA_ARCH_FEAT_SM100_ALL)
#define HAS_TCGEN05 1
#endif

// fp32 intermediate ping-pong buffers
__device__ float g_buf0[500 * DD];
__device__ float g_buf1[250 * DD];

// ---------------- PTX helpers ----------------
__device__ __forceinline__ uint32_t smem_u32(const void* p) {
    uint32_t a;
    asm("{ .reg .u64 t; cvta.to.shared.u64 t, %1; cvt.u32.u64 %0, t; }" : "=r"(a) : "l"(p));
    return a;
}
__device__ __forceinline__ uint32_t elect_one() {
    uint32_t p;
    asm volatile("{ .reg .pred p; elect.sync _|p, 0xFFFFFFFF; selp.b32 %0,1,0,p; }" : "=r"(p));
    return p;
}
__device__ __forceinline__ void mbar_wait(uint32_t addr, uint32_t parity) {
    asm volatile(
        "{\n\t.reg .pred P;\n\t"
        "WL_%=:\n\t"
        "mbarrier.try_wait.parity.acquire.cta.shared::cta.b64 P, [%0], %1, 0x989680;\n\t"
        "@!P bra WL_%=;\n\t}"
        :: "r"(addr), "r"(parity) : "memory");
}
// K-major SW128 descriptor (LBO=1, SBO=64), 128-byte rows — validated config.
__device__ __forceinline__ uint64_t desc_k(uint32_t addr) {
    return ((uint64_t)2 << 61) | ((uint64_t)1 << 46) | ((uint64_t)64 << 32) |
           ((uint64_t)1 << 16) | ((addr >> 4) & 0x3FFF);
}
// idesc: f32 accum, bf16 A/B, N=128, M=128, both K-major (validated in R5)
#define IDESC 0x8200490u

#ifdef HAS_TCGEN05
__device__ __forceinline__ void mma_bf16(uint32_t d, uint64_t a, uint64_t b, uint32_t en) {
    asm volatile(
        "{\n\t.reg .pred p;\n\tsetp.ne.u32 p, %5, 0;\n\t"
        "tcgen05.mma.cta_group::1.kind::f16 [%0], %1, %2, %3, {%4,%4,%4,%4}, p;\n\t}"
        :: "r"(d), "l"(a), "l"(b), "r"(IDESC), "r"(0u), "r"(en) : "memory");
}
#define LDTM_X32(r, addr)                                                        \
    asm volatile(                                                                \
        "tcgen05.ld.sync.aligned.32x32b.x32.b32 "                                \
        "{%0,%1,%2,%3,%4,%5,%6,%7,%8,%9,%10,%11,%12,%13,%14,%15,"                \
        "%16,%17,%18,%19,%20,%21,%22,%23,%24,%25,%26,%27,%28,%29,%30,%31},[%32];"\
        : "=r"((r)[0]), "=r"((r)[1]), "=r"((r)[2]), "=r"((r)[3]),                \
          "=r"((r)[4]), "=r"((r)[5]), "=r"((r)[6]), "=r"((r)[7]),                \
          "=r"((r)[8]), "=r"((r)[9]), "=r"((r)[10]), "=r"((r)[11]),              \
          "=r"((r)[12]), "=r"((r)[13]), "=r"((r)[14]), "=r"((r)[15]),            \
          "=r"((r)[16]), "=r"((r)[17]), "=r"((r)[18]), "=r"((r)[19]),            \
          "=r"((r)[20]), "=r"((r)[21]), "=r"((r)[22]), "=r"((r)[23]),            \
          "=r"((r)[24]), "=r"((r)[25]), "=r"((r)[26]), "=r"((r)[27]),            \
          "=r"((r)[28]), "=r"((r)[29]), "=r"((r)[30]), "=r"((r)[31])             \
        : "r"(addr))
#endif

// pack two f32 -> bf16x2 (a -> low half, b -> high half)
__device__ __forceinline__ uint32_t pack_bf2(float a, float b) {
    uint32_t r;
    asm("cvt.rn.bf16x2.f32 %0, %1, %2;" : "=r"(r) : "f"(b), "f"(a));
    return r;
}
// 3-way split of a pair: x = h + m + l (each bf16), captures full fp32 mantissa
__device__ __forceinline__ void split3_pair(float a, float b,
                                            uint32_t& h, uint32_t& m, uint32_t& l) {
    h = pack_bf2(a, b);
    float ha = __uint_as_float(h << 16);
    float hb = __uint_as_float(h & 0xffff0000u);
    float ra = a - ha, rb = b - hb;               // exact
    m = pack_bf2(ra, rb);
    float ma = __uint_as_float(m << 16);
    float mb = __uint_as_float(m & 0xffff0000u);
    l = pack_bf2(ra - ma, rb - mb);
}

// smem layout (bytes)
#define SM_TMEMP 0
#define SM_MBAR  8          // two mbarriers: +0 (even chunks), +8 (odd chunks)
#define SM_PL    1024
#define PLSZ     16384
// plane(stage s, idx i): i = 0:LH 1:LM 2:LL 3:BH 4:BM 5:BL
#define SM_PLANE(s, i) (SM_PL + ((s) * 6 + (i)) * PLSZ)
#define SM_SCR   (SM_PL + 12 * PLSZ)            // FIRST only: fp32 64x128 = 32KB
#define SM_REST  (SM_PL + 12 * PLSZ)            // 197632
#define SM_FIRST (SM_SCR + 32768)               // 230400 (<= 232448 cap)

// C_p = M[2p+1] @ M[2p], 512x512 fp32.
// FIRST: inputs raw A (M = I - A/1000 on load); right operand transposed
//        in-kernel via fp32 scratch.
// Non-FIRST: left operand (odd idx) stored normal, right (even idx) stored
//        TRANSPOSED by producing epilogue -> both load directly K-major.
// Epilogue: store transposed iff (p even) && !force_normal.
// Pipeline: lag-2 double buffer. Chunk c commits to mbar[c&1]; on each
// barrier consecutive events are 2 chunks apart and the wait->sync->issue
// order bounds it to <=1 phase ahead of any waiter (parity-safe).
template <bool FIRST>
__global__ void __launch_bounds__(256) tree_gemm(const float* __restrict__ in,
                                                 float* __restrict__ out,
                                                 int force_normal)
{
#ifndef HAS_TCGEN05
    __trap();
#else
    extern __shared__ char smem[];
    const uint32_t sb = smem_u32(smem);
    const int tid = threadIdx.x;
    const int wid = tid >> 5, lid = tid & 31;
    const int p = blockIdx.z;
    const float* __restrict__ L = in + (size_t)(2 * p + 1) * DD;
    const float* __restrict__ R = in + (size_t)(2 * p) * DD;
    float* __restrict__ C = out + (size_t)p * DD;
    const int bm = blockIdx.y * 128, bn = blockIdx.x * 128;
    const bool storeT = ((p & 1) == 0) && !force_normal;

    if (wid == 0) {
        asm volatile("tcgen05.alloc.cta_group::1.sync.aligned.shared::cta.b32 [%0], %1;"
                     :: "r"(sb + SM_TMEMP), "r"(128u) : "memory");
        asm volatile("tcgen05.relinquish_alloc_permit.cta_group::1.sync.aligned;");
    }
    if (tid == 0) {
        asm volatile("mbarrier.init.shared.b64 [%0], %1;" :: "r"(sb + SM_MBAR), "r"(1u) : "memory");
        asm volatile("mbarrier.init.shared.b64 [%0], %1;" :: "r"(sb + SM_MBAR + 8), "r"(1u) : "memory");
    }
    __syncthreads();
    uint32_t tmem;
    asm volatile("ld.shared.b32 %0,[%1];" : "=r"(tmem) : "r"(sb + SM_TMEMP));

    // LDG assignments (tile rows x 64-k chunk)
    const int lm  = tid >> 4;         // row base (0..15): rows lm + 16*i
    const int lk4 = (tid & 15) * 4;   // k-col within chunk (0..60)
    // FIRST R-side assignments
    const int rk  = tid >> 5;         // k-row base (0..7): rows rk + 8*i
    const int rn4 = (tid & 31) * 4;   // n-col (0..124)
    // FIRST column-phase (transpose)
    const int cn  = tid & 127;        // B row index n
    const int ck0 = (tid >> 7) * 32;  // k base: 0 or 32
    const uint32_t swx = (uint32_t)((cn & 7) << 4);

    float4 lreg[8], rreg[8];
    {
        const float* Lp = L + (size_t)(bm + lm) * D + lk4;
        #pragma unroll
        for (int i = 0; i < 8; i++)
            lreg[i] = *(const float4*)(Lp + (size_t)16 * i * D);
        if (FIRST) {
            const float* Rp = R + (size_t)rk * D + bn + rn4;
            #pragma unroll
            for (int i = 0; i < 8; i++)
                rreg[i] = *(const float4*)(Rp + (size_t)8 * i * D);
        } else {
            const float* Rp = R + (size_t)(bn + lm) * D + lk4;   // B stored X^T
            #pragma unroll
            for (int i = 0; i < 8; i++)
                rreg[i] = *(const float4*)(Rp + (size_t)16 * i * D);
        }
    }

    for (int c = 0; c < 8; c++) {
        const int s = c & 1;

        if (FIRST) {
            // stage R chunk into fp32 scratch (transform applied)
            #pragma unroll
            for (int i = 0; i < 8; i++) {
                float4 v = rreg[i];
                const int kk = rk + 8 * i;
                const int gr = c * 64 + kk, gc = bn + rn4;
                v.x = fmaf(v.x, -1e-3f, (gr == gc + 0) ? 1.f : 0.f);
                v.y = fmaf(v.y, -1e-3f, (gr == gc + 1) ? 1.f : 0.f);
                v.z = fmaf(v.z, -1e-3f, (gr == gc + 2) ? 1.f : 0.f);
                v.w = fmaf(v.w, -1e-3f, (gr == gc + 3) ? 1.f : 0.f);
                *(float4*)(smem + SM_SCR + (size_t)kk * 512 + (size_t)rn4 * 4) = v;
            }
        }

        // wait for MMA of chunk c-2 (same stage): barrier (c&1), phase (c-2)/2
        if (c >= 2)
            mbar_wait(sb + SM_MBAR + (uint32_t)(s * 8), (uint32_t)(((c - 2) >> 1) & 1));

        // L: split3 + swizzled K-major store
        #pragma unroll
        for (int i = 0; i < 8; i++) {
            float4 v = lreg[i];
            const int m = lm + 16 * i;
            if (FIRST) {
                const int gr = bm + m, gc = c * 64 + lk4;
                v.x = fmaf(v.x, -1e-3f, (gr == gc + 0) ? 1.f : 0.f);
                v.y = fmaf(v.y, -1e-3f, (gr == gc + 1) ? 1.f : 0.f);
                v.z = fmaf(v.z, -1e-3f, (gr == gc + 2) ? 1.f : 0.f);
                v.w = fmaf(v.w, -1e-3f, (gr == gc + 3) ? 1.f : 0.f);
            }
            uint32_t h0, m0, l0, h1, m1, l1;
            split3_pair(v.x, v.y, h0, m0, l0);
            split3_pair(v.z, v.w, h1, m1, l1);
            uint32_t off = (uint32_t)(m * 128 + lk4 * 2);
            off ^= (off >> 3) & 0x70;
            *(uint2*)(smem + SM_PLANE(s, 0) + off) = make_uint2(h0, h1);
            *(uint2*)(smem + SM_PLANE(s, 1) + off) = make_uint2(m0, m1);
            *(uint2*)(smem + SM_PLANE(s, 2) + off) = make_uint2(l0, l1);
        }

        if (!FIRST) {
            // B: direct K-major loads (already transposed in gmem)
            #pragma unroll
            for (int i = 0; i < 8; i++) {
                float4 v = rreg[i];
                const int n = lm + 16 * i;
                uint32_t h0, m0, l0, h1, m1, l1;
                split3_pair(v.x, v.y, h0, m0, l0);
                split3_pair(v.z, v.w, h1, m1, l1);
                uint32_t off = (uint32_t)(n * 128 + lk4 * 2);
                off ^= (off >> 3) & 0x70;
                *(uint2*)(smem + SM_PLANE(s, 3) + off) = make_uint2(h0, h1);
                *(uint2*)(smem + SM_PLANE(s, 4) + off) = make_uint2(m0, m1);
                *(uint2*)(smem + SM_PLANE(s, 5) + off) = make_uint2(l0, l1);
            }
            __syncthreads();
        } else {
            __syncthreads();   // scratch + L visible
            // column phase: transpose scratch -> B planes
            const float* scr = (const float*)(smem + SM_SCR);
            #pragma unroll
            for (int j = 0; j < 4; j++) {
                const int kb = ck0 + 8 * j;
                float f[8];
                #pragma unroll
                for (int i = 0; i < 8; i++) f[i] = scr[(kb + i) * 128 + cn];
                uint32_t h[4], mm_[4], l[4];
                #pragma unroll
                for (int q = 0; q < 4; q++)
                    split3_pair(f[2 * q], f[2 * q + 1], h[q], mm_[q], l[q]);
                const uint32_t off = (uint32_t)(cn * 128) + (((uint32_t)(kb * 2)) ^ swx);
                *(uint4*)(smem + SM_PLANE(s, 3) + off) = make_uint4(h[0], h[1], h[2], h[3]);
                *(uint4*)(smem + SM_PLANE(s, 4) + off) = make_uint4(mm_[0], mm_[1], mm_[2], mm_[3]);
                *(uint4*)(smem + SM_PLANE(s, 5) + off) = make_uint4(l[0], l[1], l[2], l[3]);
            }
            __syncthreads();
        }

        if (wid == 0) {
            asm volatile("fence.proxy.async.shared::cta;" ::: "memory");
            if (elect_one()) {
                // terms: (Lh,Bh) (Lh,Bm) (Lm,Bh) (Lm,Bm) (Lh,Bl) (Ll,Bh)
                const int ta[6] = {0, 0, 1, 1, 0, 2};
                const int tb[6] = {3, 4, 3, 4, 5, 3};
                #pragma unroll
                for (int t = 0; t < 6; t++) {
                    const uint64_t ad = desc_k(sb + SM_PLANE(s, ta[t]));
                    const uint64_t bd = desc_k(sb + SM_PLANE(s, tb[t]));
                    #pragma unroll
                    for (int ks = 0; ks < 4; ks++)
                        mma_bf16(tmem, ad + ks * 2, bd + ks * 2,
                                 (c == 0 && t == 0 && ks == 0) ? 0u : 1u);
                }
                asm volatile(
                    "tcgen05.commit.cta_group::1.mbarrier::arrive::one.shared::cluster.b64 [%0];"
                    :: "r"(sb + SM_MBAR + (uint32_t)(s * 8)) : "memory");
            }
        }

        // prefetch next chunk (overlaps MMA)
        if (c < 7) {
            const float* Lp = L + (size_t)(bm + lm) * D + (c + 1) * 64 + lk4;
            #pragma unroll
            for (int i = 0; i < 8; i++)
                lreg[i] = *(const float4*)(Lp + (size_t)16 * i * D);
            if (FIRST) {
                const float* Rp = R + (size_t)((c + 1) * 64 + rk) * D + bn + rn4;
                #pragma unroll
                for (int i = 0; i < 8; i++)
                    rreg[i] = *(const float4*)(Rp + (size_t)8 * i * D);
            } else {
                const float* Rp = R + (size_t)(bn + lm) * D + (c + 1) * 64 + lk4;
                #pragma unroll
                for (int i = 0; i < 8; i++)
                    rreg[i] = *(const float4*)(Rp + (size_t)16 * i * D);
            }
        }
    }
    // final completions: chunk 6 = even barrier phase 3; chunk 7 = odd phase 3.
    // In-loop waits consumed phases 0-2 on each barrier; both bounded (<=4).
    mbar_wait(sb + SM_MBAR, 1u);
    mbar_wait(sb + SM_MBAR + 8, 1u);
    asm volatile("tcgen05.fence::after_thread_sync;" ::: "memory");

    // epilogue
    {
        uint32_t r0[32], r1[32];
        const int ch = (wid >= 4) ? 64 : 0;
        const int m0 = (wid & 3) * 32;
        LDTM_X32(r0, tmem + (uint32_t)ch);
        LDTM_X32(r1, tmem + (uint32_t)ch + 32);
        asm volatile("tcgen05.wait::ld.sync.aligned;" ::: "memory");

        if (!storeT) {
            const int row = bm + m0 + lid;
            float* cp = C + (size_t)row * D + bn + ch;
            #pragma unroll
            for (int j = 0; j < 32; j += 4)
                *(float4*)(cp + j) = make_float4(
                    __uint_as_float(r0[j]), __uint_as_float(r0[j + 1]),
                    __uint_as_float(r0[j + 2]), __uint_as_float(r0[j + 3]));
            #pragma unroll
            for (int j = 0; j < 32; j += 4)
                *(float4*)(cp + 32 + j) = make_float4(
                    __uint_as_float(r1[j]), __uint_as_float(r1[j + 1]),
                    __uint_as_float(r1[j + 2]), __uint_as_float(r1[j + 3]));
        } else {
            // transposed store via per-warp smem bounce (planes are free now)
            float* ws = (float*)(smem + SM_PL + wid * (32 * 33 * 4));
            #pragma unroll
            for (int pass = 0; pass < 2; pass++) {
                const uint32_t* rr = pass ? r1 : r0;
                #pragma unroll
                for (int cc = 0; cc < 32; cc++)
                    ws[cc * 33 + lid] = __uint_as_float(rr[cc]);
                __syncwarp();
                float* gp = C + (size_t)(bn + ch + pass * 32 + lid) * D + bm + m0;
                #pragma unroll
                for (int r = 0; r < 32; r += 4) {
                    float4 v = make_float4(ws[lid * 33 + r],     ws[lid * 33 + r + 1],
                                           ws[lid * 33 + r + 2], ws[lid * 33 + r + 3]);
                    *(float4*)(gp + r) = v;
                }
                __syncwarp();
            }
        }
    }
    __syncthreads();
    if (wid == 0) {
        asm volatile("tcgen05.dealloc.cta_group::1.sync.aligned.b32 %0, %1;"
                     :: "r"(tmem), "r"(128u));
    }
#endif  // HAS_TCGEN05
}

// out = in^T  (512x512 fp32)
__global__ void transpose512(const float* __restrict__ in, float* __restrict__ out)
{
    __shared__ float t[32][33];
    const int bx = blockIdx.x * 32, by = blockIdx.y * 32;
    const int x = threadIdx.x, y0 = threadIdx.y;
    #pragma unroll
    for (int dy = 0; dy < 32; dy += 8)
        t[y0 + dy][x] = in[(size_t)(by + y0 + dy) * D + bx + x];
    __syncthreads();
    #pragma unroll
    for (int dy = 0; dy < 32; dy += 8)
        out[(size_t)(bx + y0 + dy) * D + by + x] = t[x][y0 + dy];
}

extern "C" void kernel_launch(void* const* d_in, const int* in_sizes, int n_in,
                              void* d_out, int out_size)
{
    (void)in_sizes; (void)n_in; (void)out_size;
    const float* A = (const float*)d_in[0];
    float* out = (float*)d_out;

    float *b0 = nullptr, *b1 = nullptr;
    cudaGetSymbolAddress((void**)&b0, g_buf0);
    cudaGetSymbolAddress((void**)&b1, g_buf1);

    cudaFuncSetAttribute((const void*)tree_gemm<true>,
                         cudaFuncAttributeMaxDynamicSharedMemorySize, SM_FIRST);
    cudaFuncSetAttribute((const void*)tree_gemm<false>,
                         cudaFuncAttributeMaxDynamicSharedMemorySize, SM_REST);

    // Level 1: 1000 raw A -> 500 products; outputs stored T (p even) / N (p odd)
    tree_gemm<true><<<dim3(4, 4, 500), 256, SM_FIRST>>>(A, b0, 0);

    int cnt = 500;
    float* src = b0;
    float* dst = b1;
    while (cnt > 1) {
        const int pairs = cnt >> 1;
        float* o = (cnt == 2) ? out : dst;
        tree_gemm<false><<<dim3(4, 4, pairs), 256, SM_REST>>>(src, o, (cnt == 2) ? 1 : 0);
        if (cnt & 1) {
            // leftover src[cnt-1] (even idx -> stored T) -> new index `pairs`
            const float* lv = src + (size_t)(cnt - 1) * DD;
            float* ov = o + (size_t)pairs * DD;
            if (pairs & 1)  // new role: left -> needs N: transpose
                transpose512<<<dim3(16, 16), dim3(32, 8)>>>(lv, ov);
            else            // new role: right -> stays T: plain copy
                cudaMemcpyAsync(ov, lv, DD * sizeof(float), cudaMemcpyDeviceToDevice);
        }
        cnt = pairs + (cnt & 1);
        float* t = src; src = dst; dst = t;
    }
}

// round 14
// speedup vs baseline: 1.8259x; 1.8259x over previous
#include <cuda_runtime.h>
#include <cuda_bf16.h>
#include <cstdint>

#define D  512
#define DD (D * D)

#if !defined(__CUDA_ARCH__) || defined(__CUDA_ARCH_FEAT_SM103_ALL) || defined(__CUDA_ARCH_FEAT_SM100_ALL)
#define HAS_TCGEN05 1
#endif

// fp32 intermediate ping-pong buffers (R5/R7's exact buffers)
__device__ float g_buf0[500 * DD];
__device__ float g_buf1[250 * DD];

// ---------------- PTX helpers (validated R5/R7) ----------------
__device__ __forceinline__ uint32_t smem_u32(const void* p) {
    uint32_t a;
    asm("{ .reg .u64 t; cvta.to.shared.u64 t, %1; cvt.u32.u64 %0, t; }" : "=r"(a) : "l"(p));
    return a;
}
__device__ __forceinline__ uint32_t elect_one() {
    uint32_t p;
    asm volatile("{ .reg .pred p; elect.sync _|p, 0xFFFFFFFF; selp.b32 %0,1,0,p; }" : "=r"(p));
    return p;
}
__device__ __forceinline__ void mbar_wait(uint32_t addr, uint32_t parity) {
    asm volatile(
        "{\n\t.reg .pred P;\n\t"
        "WL_%=:\n\t"
        "mbarrier.try_wait.parity.acquire.cta.shared::cta.b64 P, [%0], %1, 0x989680;\n\t"
        "@!P bra WL_%=;\n\t}"
        :: "r"(addr), "r"(parity) : "memory");
}
__device__ __forceinline__ uint64_t desc_k(uint32_t addr) {
    return ((uint64_t)2 << 61) | ((uint64_t)1 << 46) | ((uint64_t)64 << 32) |
           ((uint64_t)1 << 16) | ((addr >> 4) & 0x3FFF);
}
// idesc: f32 accum, bf16 A/B, N=128, M=128, both K-major (validated R5/R7)
#define IDESC 0x8200490u

#ifdef HAS_TCGEN05
__device__ __forceinline__ void mma_bf16(uint32_t d, uint64_t a, uint64_t b, uint32_t en) {
    asm volatile(
        "{\n\t.reg .pred p;\n\tsetp.ne.u32 p, %5, 0;\n\t"
        "tcgen05.mma.cta_group::1.kind::f16 [%0], %1, %2, %3, {%4,%4,%4,%4}, p;\n\t}"
        :: "r"(d), "l"(a), "l"(b), "r"(IDESC), "r"(0u), "r"(en) : "memory");
}
#define LDTM_X32(r, addr)                                                        \
    asm volatile(                                                                \
        "tcgen05.ld.sync.aligned.32x32b.x32.b32 "                                \
        "{%0,%1,%2,%3,%4,%5,%6,%7,%8,%9,%10,%11,%12,%13,%14,%15,"                \
        "%16,%17,%18,%19,%20,%21,%22,%23,%24,%25,%26,%27,%28,%29,%30,%31},[%32];"\
        : "=r"((r)[0]), "=r"((r)[1]), "=r"((r)[2]), "=r"((r)[3]),                \
          "=r"((r)[4]), "=r"((r)[5]), "=r"((r)[6]), "=r"((r)[7]),                \
          "=r"((r)[8]), "=r"((r)[9]), "=r"((r)[10]), "=r"((r)[11]),              \
          "=r"((r)[12]), "=r"((r)[13]), "=r"((r)[14]), "=r"((r)[15]),            \
          "=r"((r)[16]), "=r"((r)[17]), "=r"((r)[18]), "=r"((r)[19]),            \
          "=r"((r)[20]), "=r"((r)[21]), "=r"((r)[22]), "=r"((r)[23]),            \
          "=r"((r)[24]), "=r"((r)[25]), "=r"((r)[26]), "=r"((r)[27]),            \
          "=r"((r)[28]), "=r"((r)[29]), "=r"((r)[30]), "=r"((r)[31])             \
        : "r"(addr))
#endif

__device__ __forceinline__ uint32_t pack_bf2(float a, float b) {
    uint32_t r;
    asm("cvt.rn.bf16x2.f32 %0, %1, %2;" : "=r"(r) : "f"(b), "f"(a));
    return r;
}
__device__ __forceinline__ void split_pair(float a, float b, uint32_t& h, uint32_t& l) {
    h = pack_bf2(a, b);
    float ha = __uint_as_float(h << 16);
    float hb = __uint_as_float(h & 0xffff0000u);
    l = pack_bf2(a - ha, b - hb);
}

// smem layout (R5's exact map)
#define SM_TMEMP 0
#define SM_MBAR  8
#define SM_LH    1024
#define SM_LL    (SM_LH + 16384)
#define SM_BH    (SM_LL + 16384)
#define SM_BL    (SM_BH + 16384)
#define SM_SCR   (SM_BL + 16384)
#define SM_REST  (SM_BL + 16384)     // 66560 (non-first: no scratch)
#define SM_FIRST (SM_SCR + 32768)    // 99328

// C_p = M[2p+1] @ M[2p], 512x512 fp32.
// FIRST: inputs raw A (M = I - A/1000 on load); right operand transposed
//        in-kernel via fp32 scratch (R5's validated path).
// Non-FIRST: left operand (odd idx) stored row-major, right (even idx)
//        stored TRANSPOSED by producing epilogue -> both load direct K-major
//        (R7's validated path).
// Epilogue: store transposed iff (p even) && !force_normal (R7 validated).
template <bool FIRST>
__global__ void __launch_bounds__(256) tree_gemm(const float* __restrict__ in,
                                                 float* __restrict__ out,
                                                 int force_normal)
{
#ifndef HAS_TCGEN05
    __trap();
#else
    extern __shared__ char smem[];
    const uint32_t sb = smem_u32(smem);
    const int tid = threadIdx.x;
    const int wid = tid >> 5, lid = tid & 31;
    const int p = blockIdx.z;
    const float* __restrict__ L = in + (size_t)(2 * p + 1) * DD;
    const float* __restrict__ R = in + (size_t)(2 * p) * DD;
    float* __restrict__ C = out + (size_t)p * DD;
    const int bm = blockIdx.y * 128, bn = blockIdx.x * 128;
    const bool storeT = ((p & 1) == 0) && !force_normal;

    if (wid == 0) {
        asm volatile("tcgen05.alloc.cta_group::1.sync.aligned.shared::cta.b32 [%0], %1;"
                     :: "r"(sb + SM_TMEMP), "r"(128u) : "memory");
        asm volatile("tcgen05.relinquish_alloc_permit.cta_group::1.sync.aligned;");
    }
    if (tid == 0) {
        asm volatile("mbarrier.init.shared.b64 [%0], %1;" :: "r"(sb + SM_MBAR), "r"(1u) : "memory");
    }
    __syncthreads();
    uint32_t tmem;
    asm volatile("ld.shared.b32 %0,[%1];" : "=r"(tmem) : "r"(sb + SM_TMEMP));

    // LDG assignments
    const int lm  = tid >> 4;         // row base (0..15): rows lm + 16*i
    const int lk4 = (tid & 15) * 4;   // k-col within chunk (0..60)
    // FIRST R-side assignments
    const int rk  = tid >> 5;         // k-row base (0..7): rows rk + 8*i
    const int rn4 = (tid & 31) * 4;   // n-col (0..124)
    // FIRST column-phase (transpose)
    const int cn  = tid & 127;
    const int ck0 = (tid >> 7) * 32;
    const uint32_t swx = (uint32_t)((cn & 7) << 4);

    float4 lreg[8], rreg[8];
    {
        const float* Lp = L + (size_t)(bm + lm) * D + lk4;
        #pragma unroll
        for (int i = 0; i < 8; i++)
            lreg[i] = *(const float4*)(Lp + (size_t)16 * i * D);
        if (FIRST) {
            const float* Rp = R + (size_t)rk * D + bn + rn4;
            #pragma unroll
            for (int i = 0; i < 8; i++)
                rreg[i] = *(const float4*)(Rp + (size_t)8 * i * D);
        } else {
            const float* Rp = R + (size_t)(bn + lm) * D + lk4;   // B stored X^T
            #pragma unroll
            for (int i = 0; i < 8; i++)
                rreg[i] = *(const float4*)(Rp + (size_t)16 * i * D);
        }
    }

    for (int c = 0; c < 8; c++) {
        if (FIRST) {
            // stage R chunk into fp32 scratch (transform applied); scratch is
            // not read by MMA, safe before the wait.
            #pragma unroll
            for (int i = 0; i < 8; i++) {
                float4 v = rreg[i];
                const int kk = rk + 8 * i;
                const int gr = c * 64 + kk, gc = bn + rn4;
                v.x = fmaf(v.x, -1e-3f, (gr == gc + 0) ? 1.f : 0.f);
                v.y = fmaf(v.y, -1e-3f, (gr == gc + 1) ? 1.f : 0.f);
                v.z = fmaf(v.z, -1e-3f, (gr == gc + 2) ? 1.f : 0.f);
                v.w = fmaf(v.w, -1e-3f, (gr == gc + 3) ? 1.f : 0.f);
                *(float4*)(smem + SM_SCR + (size_t)kk * 512 + (size_t)rn4 * 4) = v;
            }
        }

        if (c > 0) mbar_wait(sb + SM_MBAR, (uint32_t)((c - 1) & 1));

        // L: transform(FIRST) + split + swizzled K-major STS
        #pragma unroll
        for (int i = 0; i < 8; i++) {
            float4 v = lreg[i];
            const int m = lm + 16 * i;
            if (FIRST) {
                const int gr = bm + m, gc = c * 64 + lk4;
                v.x = fmaf(v.x, -1e-3f, (gr == gc + 0) ? 1.f : 0.f);
                v.y = fmaf(v.y, -1e-3f, (gr == gc + 1) ? 1.f : 0.f);
                v.z = fmaf(v.z, -1e-3f, (gr == gc + 2) ? 1.f : 0.f);
                v.w = fmaf(v.w, -1e-3f, (gr == gc + 3) ? 1.f : 0.f);
            }
            uint32_t h0, l0, h1, l1;
            split_pair(v.x, v.y, h0, l0);
            split_pair(v.z, v.w, h1, l1);
            uint32_t off = (uint32_t)(m * 128 + lk4 * 2);
            off ^= (off >> 3) & 0x70;
            *(uint2*)(smem + SM_LH + off) = make_uint2(h0, h1);
            *(uint2*)(smem + SM_LL + off) = make_uint2(l0, l1);
        }

        if (!FIRST) {
            // B: direct K-major loads (already transposed in gmem)
            #pragma unroll
            for (int i = 0; i < 8; i++) {
                float4 v = rreg[i];
                const int n = lm + 16 * i;
                uint32_t h0, l0, h1, l1;
                split_pair(v.x, v.y, h0, l0);
                split_pair(v.z, v.w, h1, l1);
                uint32_t off = (uint32_t)(n * 128 + lk4 * 2);
                off ^= (off >> 3) & 0x70;
                *(uint2*)(smem + SM_BH + off) = make_uint2(h0, h1);
                *(uint2*)(smem + SM_BL + off) = make_uint2(l0, l1);
            }
            __syncthreads();
        } else {
            __syncthreads();   // scratch + L visible
            // column phase: transpose scratch -> B planes (R5 exact)
            const float* scr = (const float*)(smem + SM_SCR);
            #pragma unroll
            for (int j = 0; j < 4; j++) {
                const int kb = ck0 + 8 * j;
                float f[8];
                #pragma unroll
                for (int i = 0; i < 8; i++) f[i] = scr[(kb + i) * 128 + cn];
                uint32_t h[4], l[4];
                #pragma unroll
                for (int q = 0; q < 4; q++)
                    split_pair(f[2 * q], f[2 * q + 1], h[q], l[q]);
                const uint32_t off = (uint32_t)(cn * 128) + (((uint32_t)(kb * 2)) ^ swx);
                *(uint4*)(smem + SM_BH + off) = make_uint4(h[0], h[1], h[2], h[3]);
                *(uint4*)(smem + SM_BL + off) = make_uint4(l[0], l[1], l[2], l[3]);
            }
            __syncthreads();
        }

        if (wid == 0) {
            asm volatile("fence.proxy.async.shared::cta;" ::: "memory");
            if (elect_one()) {
                const uint64_t ah = desc_k(sb + SM_LH);
                const uint64_t al = desc_k(sb + SM_LL);
                const uint64_t bh = desc_k(sb + SM_BH);
                const uint64_t bl = desc_k(sb + SM_BL);
                #pragma unroll
                for (int ks = 0; ks < 4; ks++)
                    mma_bf16(tmem, ah + ks * 2, bh + ks * 2, (c == 0 && ks == 0) ? 0u : 1u);
                #pragma unroll
                for (int ks = 0; ks < 4; ks++)
                    mma_bf16(tmem, ah + ks * 2, bl + ks * 2, 1u);
                #pragma unroll
                for (int ks = 0; ks < 4; ks++)
                    mma_bf16(tmem, al + ks * 2, bh + ks * 2, 1u);
                asm volatile(
                    "tcgen05.commit.cta_group::1.mbarrier::arrive::one.shared::cluster.b64 [%0];"
                    :: "r"(sb + SM_MBAR) : "memory");
            }
        }

        // prefetch next chunk (overlaps MMA)
        if (c < 7) {
            const float* Lp = L + (size_t)(bm + lm) * D + (c + 1) * 64 + lk4;
            #pragma unroll
            for (int i = 0; i < 8; i++)
                lreg[i] = *(const float4*)(Lp + (size_t)16 * i * D);
            if (FIRST) {
                const float* Rp = R + (size_t)((c + 1) * 64 + rk) * D + bn + rn4;
                #pragma unroll
                for (int i = 0; i < 8; i++)
                    rreg[i] = *(const float4*)(Rp + (size_t)8 * i * D);
            } else {
                const float* Rp = R + (size_t)(bn + lm) * D + (c + 1) * 64 + lk4;
                #pragma unroll
                for (int i = 0; i < 8; i++)
                    rreg[i] = *(const float4*)(Rp + (size_t)16 * i * D);
            }
        }
    }
    mbar_wait(sb + SM_MBAR, 1u);  // completion 7 (in-loop waits consumed 0-6)
    asm volatile("tcgen05.fence::after_thread_sync;" ::: "memory");

    // epilogue (R7 exact): normal or transposed store
    {
        uint32_t r0[32], r1[32];
        const int ch = (wid >= 4) ? 64 : 0;
        const int m0 = (wid & 3) * 32;
        LDTM_X32(r0, tmem + (uint32_t)ch);
        LDTM_X32(r1, tmem + (uint32_t)ch + 32);
        asm volatile("tcgen05.wait::ld.sync.aligned;" ::: "memory");

        if (!storeT) {
            const int row = bm + m0 + lid;
            float* cp = C + (size_t)row * D + bn + ch;
            #pragma unroll
            for (int j = 0; j < 32; j += 4)
                *(float4*)(cp + j) = make_float4(
                    __uint_as_float(r0[j]), __uint_as_float(r0[j + 1]),
                    __uint_as_float(r0[j + 2]), __uint_as_float(r0[j + 3]));
            #pragma unroll
            for (int j = 0; j < 32; j += 4)
                *(float4*)(cp + 32 + j) = make_float4(
                    __uint_as_float(r1[j]), __uint_as_float(r1[j + 1]),
                    __uint_as_float(r1[j + 2]), __uint_as_float(r1[j + 3]));
        } else {
            float* ws = (float*)(smem + SM_LH + wid * (32 * 33 * 4));
            #pragma unroll
            for (int pass = 0; pass < 2; pass++) {
                const uint32_t* rr = pass ? r1 : r0;
                #pragma unroll
                for (int cc = 0; cc < 32; cc++)
                    ws[cc * 33 + lid] = __uint_as_float(rr[cc]);
                __syncwarp();
                float* gp = C + (size_t)(bn + ch + pass * 32 + lid) * D + bm + m0;
                #pragma unroll
                for (int r = 0; r < 32; r += 4) {
                    float4 v = make_float4(ws[lid * 33 + r],     ws[lid * 33 + r + 1],
                                           ws[lid * 33 + r + 2], ws[lid * 33 + r + 3]);
                    *(float4*)(gp + r) = v;
                }
                __syncwarp();
            }
        }
    }
    __syncthreads();
    if (wid == 0) {
        asm volatile("tcgen05.dealloc.cta_group::1.sync.aligned.b32 %0, %1;"
                     :: "r"(tmem), "r"(128u));
    }
#endif  // HAS_TCGEN05
}

// out = in^T  (512x512 fp32) — R7 validated
__global__ void transpose512(const float* __restrict__ in, float* __restrict__ out)
{
    __shared__ float t[32][33];
    const int bx = blockIdx.x * 32, by = blockIdx.y * 32;
    const int x = threadIdx.x, y0 = threadIdx.y;
    #pragma unroll
    for (int dy = 0; dy < 32; dy += 8)
        t[y0 + dy][x] = in[(size_t)(by + y0 + dy) * D + bx + x];
    __syncthreads();
    #pragma unroll
    for (int dy = 0; dy < 32; dy += 8)
        out[(size_t)(bx + y0 + dy) * D + by + x] = t[x][y0 + dy];
}

extern "C" void kernel_launch(void* const* d_in, const int* in_sizes, int n_in,
                              void* d_out, int out_size)
{
    (void)in_sizes; (void)n_in; (void)out_size;
    const float* A = (const float*)d_in[0];
    float* out = (float*)d_out;

    float *b0 = nullptr, *b1 = nullptr;
    cudaGetSymbolAddress((void**)&b0, g_buf0);
    cudaGetSymbolAddress((void**)&b1, g_buf1);

    cudaFuncSetAttribute((const void*)tree_gemm<true>,
                         cudaFuncAttributeMaxDynamicSharedMemorySize, SM_FIRST);
    cudaFuncSetAttribute((const void*)tree_gemm<false>,
                         cudaFuncAttributeMaxDynamicSharedMemorySize, SM_REST);

    // Level 1: 1000 raw A -> 500 products; outputs stored T (p even) / N (p odd)
    tree_gemm<true><<<dim3(4, 4, 500), 256, SM_FIRST>>>(A, b0, 0);

    int cnt = 500;
    float* src = b0;
    float* dst = b1;
    while (cnt > 1) {
        const int pairs = cnt >> 1;
        float* o = (cnt == 2) ? out : dst;
        tree_gemm<false><<<dim3(4, 4, pairs), 256, SM_REST>>>(src, o, (cnt == 2) ? 1 : 0);
        if (cnt & 1) {
            // leftover src[cnt-1] (even idx -> stored T) -> new index `pairs`
            const float* lv = src + (size_t)(cnt - 1) * DD;
            float* ov = o + (size_t)pairs * DD;
            if (pairs & 1)  // new role: left -> needs N: transpose
                transpose512<<<dim3(16, 16), dim3(32, 8)>>>(lv, ov);
            else            // new role: right -> stays T: plain copy
                cudaMemcpyAsync(ov, lv, DD * sizeof(float), cudaMemcpyDeviceToDevice);
        }
        cnt = pairs + (cnt & 1);
        float* t = src; src = dst; dst = t;
    }
}